// round 2
// baseline (speedup 1.0000x reference)
#include <cuda_runtime.h>
#include <math.h>

#define NN 50000
#define EE 800000
#define DD 128
#define HH 8
#define HIDDEN 512
#define BN_EPS 1e-5f
#define SLOPE 0.2f

// ---------------- scratch (static __device__ arrays; no allocation) ----------
__device__ float g_feat[(size_t)NN * DD];            // x @ W            25.6 MB
__device__ float g_el[NN * HH];                      // per-node left logits
__device__ float g_er[NN * HH];                      // per-node right logits
__device__ float g_denom[NN * HH];                   // softmax denominators
__device__ float g_agg[(size_t)NN * DD];             // aggregated messages
__device__ float g_mid[(size_t)NN * HIDDEN];         // hidden activations 102 MB
__device__ float g_stats[4 * DD];                    // sum1,sumsq1,sum2,sumsq2
__device__ float g_scale1[DD], g_shift1[DD];
__device__ float g_scale2[DD], g_shift2[DD];

// ---------------- utility ---------------------------------------------------
__global__ void zero_kernel(float* __restrict__ p, int n) {
    int i = blockIdx.x * blockDim.x + threadIdx.x;
    if (i < n) p[i] = 0.0f;
}

// ---------------- SGEMM: C[M,N] = op(A[M,K] @ B[K,N]) ----------------------
// BM=128, BN=64, BK=16, 256 threads, each thread computes 8x4.
// ASCALE: A element a[m,k] -> a*ascale[k] + ashift[k]   (fused BatchNorm apply)
// BIASR : add bias[n] and apply ReLU in epilogue
template <bool ASCALE, bool BIASR>
__global__ void __launch_bounds__(256)
sgemm_kernel(const float* __restrict__ A, const float* __restrict__ B,
             float* __restrict__ C, int M, int N, int K,
             const float* __restrict__ ascale, const float* __restrict__ ashift,
             const float* __restrict__ bias)
{
    __shared__ float As[16][128];      // stored transposed: As[k][m]
    __shared__ float Bs[16][68];       // padded row: 68*4=272B (16B aligned)

    const int tid = threadIdx.x;
    const int bm = blockIdx.y * 128;
    const int bn = blockIdx.x * 64;
    const int tx = tid & 15;           // 0..15
    const int ty = tid >> 4;           // 0..15
    const int row0 = ty * 8;
    const int col0 = tx * 4;

    float acc[8][4];
#pragma unroll
    for (int i = 0; i < 8; i++)
#pragma unroll
        for (int j = 0; j < 4; j++) acc[i][j] = 0.0f;

    for (int k0 = 0; k0 < K; k0 += 16) {
        // --- load A tile: 128x16 floats = 512 float4, 2 per thread ---
#pragma unroll
        for (int j = 0; j < 2; j++) {
            int idx = tid * 2 + j;            // 0..511
            int ar = idx >> 2;                // 0..127 (row in tile)
            int ac = (idx & 3) * 4;           // 0,4,8,12 (col in tile)
            float4 v = make_float4(0.f, 0.f, 0.f, 0.f);
            int grow = bm + ar;
            if (grow < M)
                v = *(const float4*)(A + (size_t)grow * K + k0 + ac);
            if (ASCALE) {
                v.x = v.x * ascale[k0 + ac + 0] + ashift[k0 + ac + 0];
                v.y = v.y * ascale[k0 + ac + 1] + ashift[k0 + ac + 1];
                v.z = v.z * ascale[k0 + ac + 2] + ashift[k0 + ac + 2];
                v.w = v.w * ascale[k0 + ac + 3] + ashift[k0 + ac + 3];
            }
            As[ac + 0][ar] = v.x;
            As[ac + 1][ar] = v.y;
            As[ac + 2][ar] = v.z;
            As[ac + 3][ar] = v.w;
        }
        // --- load B tile: 16x64 floats = 256 float4, 1 per thread ---
        {
            int br = tid >> 4;                // 0..15
            int bc = (tid & 15) * 4;          // 0..60
            float4 v = *(const float4*)(B + (size_t)(k0 + br) * N + bn + bc);
            Bs[br][bc + 0] = v.x;
            Bs[br][bc + 1] = v.y;
            Bs[br][bc + 2] = v.z;
            Bs[br][bc + 3] = v.w;
        }
        __syncthreads();

#pragma unroll
        for (int kk = 0; kk < 16; kk++) {
            float4 a0 = *(const float4*)&As[kk][row0 + 0];
            float4 a1 = *(const float4*)&As[kk][row0 + 4];
            float4 b0 = *(const float4*)&Bs[kk][col0];
            float a[8] = {a0.x, a0.y, a0.z, a0.w, a1.x, a1.y, a1.z, a1.w};
            float b[4] = {b0.x, b0.y, b0.z, b0.w};
#pragma unroll
            for (int i = 0; i < 8; i++)
#pragma unroll
                for (int j = 0; j < 4; j++)
                    acc[i][j] = fmaf(a[i], b[j], acc[i][j]);
        }
        __syncthreads();
    }

    // --- epilogue ---
    float bv[4] = {0.f, 0.f, 0.f, 0.f};
    if (BIASR) {
#pragma unroll
        for (int j = 0; j < 4; j++) bv[j] = bias[bn + col0 + j];
    }
#pragma unroll
    for (int i = 0; i < 8; i++) {
        int gr = bm + row0 + i;
        if (gr < M) {
            float4 o;
            float* op = (float*)&o;
#pragma unroll
            for (int j = 0; j < 4; j++) {
                float v = acc[i][j];
                if (BIASR) v = fmaxf(v + bv[j], 0.0f);
                op[j] = v;
            }
            *(float4*)(C + (size_t)gr * N + bn + col0) = o;
        }
    }
}

// ---------------- per-node attention logits (el, er) ------------------------
// warp per node: lane l owns float4 at column 4l; head h = l/4; quad-reduce.
__global__ void eler_kernel(const float* __restrict__ feat,
                            const float* __restrict__ attn_l,
                            const float* __restrict__ attn_r,
                            float* __restrict__ el, float* __restrict__ er)
{
    int n = (blockIdx.x * blockDim.x + threadIdx.x) >> 5;
    int lane = threadIdx.x & 31;
    if (n >= NN) return;
    float4 v  = ((const float4*)(feat + (size_t)n * DD))[lane];
    float4 al = ((const float4*)attn_l)[lane];   // attn_l is [H,16] row-major = flat 128
    float4 ar = ((const float4*)attn_r)[lane];
    float pl = v.x * al.x + v.y * al.y + v.z * al.z + v.w * al.w;
    float pr = v.x * ar.x + v.y * ar.y + v.z * ar.z + v.w * ar.w;
    pl += __shfl_xor_sync(0xFFFFFFFFu, pl, 1);
    pl += __shfl_xor_sync(0xFFFFFFFFu, pl, 2);
    pr += __shfl_xor_sync(0xFFFFFFFFu, pr, 1);
    pr += __shfl_xor_sync(0xFFFFFFFFu, pr, 2);
    if ((lane & 3) == 0) {
        int h = lane >> 2;
        el[n * HH + h] = pl;
        er[n * HH + h] = pr;
    }
}

// ---------------- edge pass 1: softmax denominators -------------------------
__global__ void edge1_kernel(const int* __restrict__ src, const int* __restrict__ dst,
                             const float* __restrict__ el, const float* __restrict__ er,
                             float* __restrict__ denom)
{
    int e = blockIdx.x * blockDim.x + threadIdx.x;
    if (e >= EE) return;
    int s = src[e], d = dst[e];
#pragma unroll
    for (int h = 0; h < HH; h++) {
        float x = el[s * HH + h] + er[d * HH + h];
        x = (x > 0.0f) ? x : SLOPE * x;
        atomicAdd(&denom[d * HH + h], expf(x));
    }
}

// ---------------- edge pass 2: weighted scatter-aggregate -------------------
// warp per edge: lane l handles float4 at column 4l (head h = l/4).
__global__ void edge2_kernel(const int* __restrict__ src, const int* __restrict__ dst,
                             const float* __restrict__ el, const float* __restrict__ er,
                             const float* __restrict__ denom,
                             const float* __restrict__ feat, float* __restrict__ agg)
{
    int e = (blockIdx.x * blockDim.x + threadIdx.x) >> 5;
    int lane = threadIdx.x & 31;
    if (e >= EE) return;
    int s = src[e], d = dst[e];
    int h = lane >> 2;
    float x = el[s * HH + h] + er[d * HH + h];
    x = (x > 0.0f) ? x : SLOPE * x;
    float alpha = expf(x) / denom[d * HH + h];
    float4 v = ((const float4*)(feat + (size_t)s * DD))[lane];
    float* out = agg + (size_t)d * DD + lane * 4;
    atomicAdd(out + 0, v.x * alpha);
    atomicAdd(out + 1, v.y * alpha);
    atomicAdd(out + 2, v.z * alpha);
    atomicAdd(out + 3, v.w * alpha);
}

// ---------------- column statistics for BatchNorm ---------------------------
__global__ void col_stats_kernel(const float* __restrict__ X, int M,
                                 float* __restrict__ sum, float* __restrict__ sumsq)
{
    int c = threadIdx.x;   // 128 threads = 128 columns
    float s = 0.0f, s2 = 0.0f;
    for (int r = blockIdx.x; r < M; r += gridDim.x) {
        float v = X[(size_t)r * DD + c];
        s += v;
        s2 += v * v;
    }
    atomicAdd(&sum[c], s);
    atomicAdd(&sumsq[c], s2);
}

__global__ void bn_finalize_kernel(const float* __restrict__ sum, const float* __restrict__ sumsq,
                                   const float* __restrict__ gamma, const float* __restrict__ beta,
                                   float* __restrict__ scale, float* __restrict__ shift, float invM)
{
    int c = threadIdx.x;
    float mu = sum[c] * invM;
    float var = sumsq[c] * invM - mu * mu;
    float sc = gamma[c] * rsqrtf(var + BN_EPS);
    scale[c] = sc;
    shift[c] = beta[c] - mu * sc;
}

__global__ void bn_apply_kernel(float* __restrict__ X,
                                const float* __restrict__ scale, const float* __restrict__ shift)
{
    int i = blockIdx.x * blockDim.x + threadIdx.x;
    if (i < NN * DD) {
        int c = i & (DD - 1);
        X[i] = X[i] * scale[c] + shift[c];
    }
}

// ---------------- launch ----------------------------------------------------
extern "C" void kernel_launch(void* const* d_in, const int* in_sizes, int n_in,
                              void* d_out, int out_size)
{
    const float* x         = (const float*)d_in[0];
    const int*   src       = (const int*)  d_in[1];
    const int*   dst       = (const int*)  d_in[2];
    const float* W         = (const float*)d_in[3];
    const float* attn_l    = (const float*)d_in[4];
    const float* attn_r    = (const float*)d_in[5];
    // d_in[6]  bias_gat : exactly absorbed by BN1 (added pre-BN, BN subtracts mean)
    const float* bn1_gamma = (const float*)d_in[7];
    const float* bn1_beta  = (const float*)d_in[8];
    const float* W1        = (const float*)d_in[9];
    const float* b1        = (const float*)d_in[10];
    const float* W2        = (const float*)d_in[11];
    // d_in[12] b2       : exactly absorbed by BN2
    const float* bn2_gamma = (const float*)d_in[13];
    const float* bn2_beta  = (const float*)d_in[14];
    float* out = (float*)d_out;

    float *p_feat, *p_el, *p_er, *p_denom, *p_agg, *p_mid, *p_stats;
    float *p_scale1, *p_shift1, *p_scale2, *p_shift2;
    cudaGetSymbolAddress((void**)&p_feat,   g_feat);
    cudaGetSymbolAddress((void**)&p_el,     g_el);
    cudaGetSymbolAddress((void**)&p_er,     g_er);
    cudaGetSymbolAddress((void**)&p_denom,  g_denom);
    cudaGetSymbolAddress((void**)&p_agg,    g_agg);
    cudaGetSymbolAddress((void**)&p_mid,    g_mid);
    cudaGetSymbolAddress((void**)&p_stats,  g_stats);
    cudaGetSymbolAddress((void**)&p_scale1, g_scale1);
    cudaGetSymbolAddress((void**)&p_shift1, g_shift1);
    cudaGetSymbolAddress((void**)&p_scale2, g_scale2);
    cudaGetSymbolAddress((void**)&p_shift2, g_shift2);

    // zero scratch that is accumulated into
    zero_kernel<<<(NN * HH + 255) / 256, 256>>>(p_denom, NN * HH);
    zero_kernel<<<(NN * DD + 255) / 256, 256>>>(p_agg, NN * DD);
    zero_kernel<<<(4 * DD + 255) / 256, 256>>>(p_stats, 4 * DD);

    // feat = x @ W  [50000,128]
    sgemm_kernel<false, false><<<dim3(DD / 64, (NN + 127) / 128), 256>>>(
        x, W, p_feat, NN, DD, DD, nullptr, nullptr, nullptr);

    // per-node attention logits
    eler_kernel<<<(NN * 32 + 255) / 256, 256>>>(p_feat, attn_l, attn_r, p_el, p_er);

    // edge softmax (max-free: exp(e)/sum(exp(e)) == reference mathematically)
    edge1_kernel<<<(EE + 255) / 256, 256>>>(src, dst, p_el, p_er, p_denom);
    edge2_kernel<<<((size_t)EE * 32 + 255) / 256, 256>>>(src, dst, p_el, p_er,
                                                         p_denom, p_feat, p_agg);

    // BN1 stats (bias_gat absorbed); apply fused into GEMM2 A-load
    col_stats_kernel<<<592, 128>>>(p_agg, NN, p_stats, p_stats + DD);
    bn_finalize_kernel<<<1, DD>>>(p_stats, p_stats + DD, bn1_gamma, bn1_beta,
                                  p_scale1, p_shift1, 1.0f / NN);

    // mid = relu(BN1(agg) @ W1 + b1)  [50000,512]
    sgemm_kernel<true, true><<<dim3(HIDDEN / 64, (NN + 127) / 128), 256>>>(
        p_agg, W1, p_mid, NN, HIDDEN, DD, p_scale1, p_shift1, b1);

    // out_pre = mid @ W2   (b2 absorbed by BN2) -> write straight to d_out
    sgemm_kernel<false, false><<<dim3(DD / 64, (NN + 127) / 128), 256>>>(
        p_mid, W2, out, NN, DD, HIDDEN, nullptr, nullptr, nullptr);

    // BN2 stats + in-place apply on d_out
    col_stats_kernel<<<592, 128>>>(out, NN, p_stats + 2 * DD, p_stats + 3 * DD);
    bn_finalize_kernel<<<1, DD>>>(p_stats + 2 * DD, p_stats + 3 * DD, bn2_gamma,
                                  bn2_beta, p_scale2, p_shift2, 1.0f / NN);
    bn_apply_kernel<<<(NN * DD + 255) / 256, 256>>>(out, p_scale2, p_shift2);
}

// round 3
// speedup vs baseline: 1.1535x; 1.1535x over previous
#include <cuda_runtime.h>
#include <math.h>

#define NN 50000
#define EE 800000
#define DD 128
#define HH 8
#define HIDDEN 512
#define BN_EPS 1e-5f
#define SLOPE 0.2f

// ---------------- scratch (static __device__ arrays; no allocation) ----------
__device__ float g_feat[(size_t)NN * DD];            // x @ W            25.6 MB
__device__ float g_el[NN * HH];
__device__ float g_er[NN * HH];
__device__ float g_denom[NN * HH];
__device__ float g_agg[(size_t)NN * DD];             // un-normalized aggregate
__device__ float g_mid[(size_t)NN * HIDDEN];         // hidden activations 102 MB
__device__ float g_stats[4 * DD];
__device__ float g_scale1[DD], g_shift1[DD];
__device__ float g_scale2[DD], g_shift2[DD];

// ---------------- utility ---------------------------------------------------
__global__ void zero_kernel(float* __restrict__ p, int n) {
    int i = blockIdx.x * blockDim.x + threadIdx.x;
    if (i < n) p[i] = 0.0f;
}

// ---------------- SGEMM: C[M,N] = op(A[M,K] @ B[K,N]) ----------------------
// BM=128, BN=128, BK=16, 256 threads, 8x8 per thread (two 4-wide fragments at
// stride 64 in each dim for conflict-free LDS.128). Register-prefetch double
// buffering of the global loads.
// ASCALE: a[m,k] -> a*ascale[k] + ashift[k]  (fused BatchNorm on A)
// BIASR : C -> relu(C + bias[n])
template <bool ASCALE, bool BIASR>
__global__ void __launch_bounds__(256, 2)
sgemm128(const float* __restrict__ A, const float* __restrict__ B,
         float* __restrict__ C, int M, int N, int K,
         const float* __restrict__ ascale, const float* __restrict__ ashift,
         const float* __restrict__ bias)
{
    __shared__ float As[16][128];      // transposed: As[k][m]
    __shared__ float Bs[16][128];      // Bs[k][n]

    const int tid = threadIdx.x;
    const int bm = blockIdx.y * 128;
    const int bn = blockIdx.x * 128;
    const int tx = tid & 15;           // 0..15 -> col fragment base
    const int ty = tid >> 4;           // 0..15 -> row fragment base

    // global-load index precompute (2 float4 per thread per tile, A and B)
    int ar[2], ac[2], br[2], bc[2];
#pragma unroll
    for (int j = 0; j < 2; j++) {
        int idx = tid * 2 + j;         // 0..511
        ar[j] = idx >> 2;              // A row in tile (0..127)
        ac[j] = (idx & 3) * 4;         // A col in tile (0,4,8,12)
        br[j] = idx >> 5;              // B row in tile (0..15)
        bc[j] = (idx & 31) * 4;        // B col in tile (0..124)
    }

    float4 pa[2], pb[2];

    auto loadA = [&](int k0) {
#pragma unroll
        for (int j = 0; j < 2; j++) {
            int grow = bm + ar[j];
            float4 v = make_float4(0.f, 0.f, 0.f, 0.f);
            if (grow < M)
                v = *(const float4*)(A + (size_t)grow * K + k0 + ac[j]);
            if (ASCALE) {
                int kc = k0 + ac[j];
                v.x = fmaf(v.x, ascale[kc + 0], ashift[kc + 0]);
                v.y = fmaf(v.y, ascale[kc + 1], ashift[kc + 1]);
                v.z = fmaf(v.z, ascale[kc + 2], ashift[kc + 2]);
                v.w = fmaf(v.w, ascale[kc + 3], ashift[kc + 3]);
            }
            pa[j] = v;
        }
    };
    auto loadB = [&](int k0) {
#pragma unroll
        for (int j = 0; j < 2; j++)
            pb[j] = *(const float4*)(B + (size_t)(k0 + br[j]) * N + bn + bc[j]);
    };

    float acc[8][8];
#pragma unroll
    for (int i = 0; i < 8; i++)
#pragma unroll
        for (int j = 0; j < 8; j++) acc[i][j] = 0.0f;

    loadA(0);
    loadB(0);

    for (int k0 = 0; k0 < K; k0 += 16) {
        // store prefetched tile to smem
#pragma unroll
        for (int j = 0; j < 2; j++) {
            As[ac[j] + 0][ar[j]] = pa[j].x;
            As[ac[j] + 1][ar[j]] = pa[j].y;
            As[ac[j] + 2][ar[j]] = pa[j].z;
            As[ac[j] + 3][ar[j]] = pa[j].w;
            *(float4*)&Bs[br[j]][bc[j]] = pb[j];
        }
        __syncthreads();

        if (k0 + 16 < K) {             // prefetch next tile (overlaps compute)
            loadA(k0 + 16);
            loadB(k0 + 16);
        }

#pragma unroll
        for (int kk = 0; kk < 16; kk++) {
            float4 a0 = *(const float4*)&As[kk][ty * 4];
            float4 a1 = *(const float4*)&As[kk][64 + ty * 4];
            float4 b0 = *(const float4*)&Bs[kk][tx * 4];
            float4 b1 = *(const float4*)&Bs[kk][64 + tx * 4];
            float a[8] = {a0.x, a0.y, a0.z, a0.w, a1.x, a1.y, a1.z, a1.w};
            float b[8] = {b0.x, b0.y, b0.z, b0.w, b1.x, b1.y, b1.z, b1.w};
#pragma unroll
            for (int i = 0; i < 8; i++)
#pragma unroll
                for (int j = 0; j < 8; j++)
                    acc[i][j] = fmaf(a[i], b[j], acc[i][j]);
        }
        __syncthreads();
    }

    // epilogue: rows {ty*4+i, 64+ty*4+i}, cols {tx*4+j, 64+tx*4+j}
#pragma unroll
    for (int ri = 0; ri < 8; ri++) {
        int lr = (ri < 4) ? (ty * 4 + ri) : (64 + ty * 4 + (ri - 4));
        int gr = bm + lr;
        if (gr >= M) continue;
#pragma unroll
        for (int cf = 0; cf < 2; cf++) {
            int gc = bn + cf * 64 + tx * 4;
            float4 o;
            float* op = (float*)&o;
#pragma unroll
            for (int j = 0; j < 4; j++) {
                float v = acc[ri][cf * 4 + j];
                if (BIASR) v = fmaxf(v + bias[gc + j], 0.0f);
                op[j] = v;
            }
            *(float4*)(C + (size_t)gr * N + gc) = o;
        }
    }
}

// ---------------- per-node attention logits (el, er) ------------------------
__global__ void eler_kernel(const float* __restrict__ feat,
                            const float* __restrict__ attn_l,
                            const float* __restrict__ attn_r,
                            float* __restrict__ el, float* __restrict__ er)
{
    int n = (blockIdx.x * blockDim.x + threadIdx.x) >> 5;
    int lane = threadIdx.x & 31;
    if (n >= NN) return;
    float4 v  = ((const float4*)(feat + (size_t)n * DD))[lane];
    float4 al = ((const float4*)attn_l)[lane];
    float4 ar = ((const float4*)attn_r)[lane];
    float pl = v.x * al.x + v.y * al.y + v.z * al.z + v.w * al.w;
    float pr = v.x * ar.x + v.y * ar.y + v.z * ar.z + v.w * ar.w;
    pl += __shfl_xor_sync(0xFFFFFFFFu, pl, 1);
    pl += __shfl_xor_sync(0xFFFFFFFFu, pl, 2);
    pr += __shfl_xor_sync(0xFFFFFFFFu, pr, 1);
    pr += __shfl_xor_sync(0xFFFFFFFFu, pr, 2);
    if ((lane & 3) == 0) {
        int h = lane >> 2;
        el[n * HH + h] = pl;
        er[n * HH + h] = pr;
    }
}

// ---------------- single edge pass: un-normalized aggregate + denom ---------
// warp per edge: lane l handles float4 at column 4l (head h = l/4).
// agg[d] += exp(leaky(e)) * feat[s];  denom[d] += exp(leaky(e))
__global__ void edge_kernel(const int* __restrict__ src, const int* __restrict__ dst,
                            const float* __restrict__ el, const float* __restrict__ er,
                            float* __restrict__ denom,
                            const float* __restrict__ feat, float* __restrict__ agg)
{
    int e = (blockIdx.x * blockDim.x + threadIdx.x) >> 5;
    int lane = threadIdx.x & 31;
    if (e >= EE) return;
    int s = src[e], d = dst[e];
    int h = lane >> 2;
    float x = el[s * HH + h] + er[d * HH + h];
    x = (x > 0.0f) ? x : SLOPE * x;
    float w = expf(x);
    if ((lane & 3) == 0) atomicAdd(&denom[d * HH + h], w);
    float4 v = ((const float4*)(feat + (size_t)s * DD))[lane];
    float* out = agg + (size_t)d * DD + lane * 4;
    atomicAdd(out + 0, v.x * w);
    atomicAdd(out + 1, v.y * w);
    atomicAdd(out + 2, v.z * w);
    atomicAdd(out + 3, v.w * w);
}

// ---------------- fused normalize + BN1 column stats ------------------------
// h = agg/denom written back in place; accumulate per-column sum/sumsq.
__global__ void div_stats_kernel(float* __restrict__ agg,
                                 const float* __restrict__ denom,
                                 float* __restrict__ sum, float* __restrict__ sumsq)
{
    int c = threadIdx.x;               // 128 threads = 128 columns
    int hh = c >> 4;
    float s = 0.0f, s2 = 0.0f;
    for (int r = blockIdx.x; r < NN; r += gridDim.x) {
        float dn = denom[r * HH + hh];
        float v = agg[(size_t)r * DD + c] / dn;
        agg[(size_t)r * DD + c] = v;
        s += v;
        s2 += v * v;
    }
    atomicAdd(&sum[c], s);
    atomicAdd(&sumsq[c], s2);
}

// ---------------- column statistics (BN2) ------------------------------------
__global__ void col_stats_kernel(const float* __restrict__ X, int M,
                                 float* __restrict__ sum, float* __restrict__ sumsq)
{
    int c = threadIdx.x;
    float s = 0.0f, s2 = 0.0f;
    for (int r = blockIdx.x; r < M; r += gridDim.x) {
        float v = X[(size_t)r * DD + c];
        s += v;
        s2 += v * v;
    }
    atomicAdd(&sum[c], s);
    atomicAdd(&sumsq[c], s2);
}

__global__ void bn_finalize_kernel(const float* __restrict__ sum, const float* __restrict__ sumsq,
                                   const float* __restrict__ gamma, const float* __restrict__ beta,
                                   float* __restrict__ scale, float* __restrict__ shift, float invM)
{
    int c = threadIdx.x;
    float mu = sum[c] * invM;
    float var = sumsq[c] * invM - mu * mu;
    float sc = gamma[c] * rsqrtf(var + BN_EPS);
    scale[c] = sc;
    shift[c] = beta[c] - mu * sc;
}

__global__ void bn_apply_kernel(float* __restrict__ X,
                                const float* __restrict__ scale, const float* __restrict__ shift)
{
    int i = blockIdx.x * blockDim.x + threadIdx.x;
    if (i < NN * DD) {
        int c = i & (DD - 1);
        X[i] = X[i] * scale[c] + shift[c];
    }
}

// ---------------- launch ----------------------------------------------------
extern "C" void kernel_launch(void* const* d_in, const int* in_sizes, int n_in,
                              void* d_out, int out_size)
{
    const float* x         = (const float*)d_in[0];
    const int*   src       = (const int*)  d_in[1];
    const int*   dst       = (const int*)  d_in[2];
    const float* W         = (const float*)d_in[3];
    const float* attn_l    = (const float*)d_in[4];
    const float* attn_r    = (const float*)d_in[5];
    // d_in[6]  bias_gat : absorbed by BN1 (constant col offset cancels vs batch mean)
    const float* bn1_gamma = (const float*)d_in[7];
    const float* bn1_beta  = (const float*)d_in[8];
    const float* W1        = (const float*)d_in[9];
    const float* b1        = (const float*)d_in[10];
    const float* W2        = (const float*)d_in[11];
    // d_in[12] b2       : absorbed by BN2
    const float* bn2_gamma = (const float*)d_in[13];
    const float* bn2_beta  = (const float*)d_in[14];
    float* out = (float*)d_out;

    float *p_feat, *p_el, *p_er, *p_denom, *p_agg, *p_mid, *p_stats;
    float *p_scale1, *p_shift1, *p_scale2, *p_shift2;
    cudaGetSymbolAddress((void**)&p_feat,   g_feat);
    cudaGetSymbolAddress((void**)&p_el,     g_el);
    cudaGetSymbolAddress((void**)&p_er,     g_er);
    cudaGetSymbolAddress((void**)&p_denom,  g_denom);
    cudaGetSymbolAddress((void**)&p_agg,    g_agg);
    cudaGetSymbolAddress((void**)&p_mid,    g_mid);
    cudaGetSymbolAddress((void**)&p_stats,  g_stats);
    cudaGetSymbolAddress((void**)&p_scale1, g_scale1);
    cudaGetSymbolAddress((void**)&p_shift1, g_shift1);
    cudaGetSymbolAddress((void**)&p_scale2, g_scale2);
    cudaGetSymbolAddress((void**)&p_shift2, g_shift2);

    // zero accumulators
    zero_kernel<<<(NN * HH + 255) / 256, 256>>>(p_denom, NN * HH);
    zero_kernel<<<(NN * DD + 255) / 256, 256>>>(p_agg, NN * DD);
    zero_kernel<<<(4 * DD + 255) / 256, 256>>>(p_stats, 4 * DD);

    // feat = x @ W  [50000,128]
    sgemm128<false, false><<<dim3(DD / 128, (NN + 127) / 128), 256>>>(
        x, W, p_feat, NN, DD, DD, nullptr, nullptr, nullptr);

    // per-node attention logits
    eler_kernel<<<(NN * 32 + 255) / 256, 256>>>(p_feat, attn_l, attn_r, p_el, p_er);

    // single-pass edge aggregation (un-normalized) + denominators
    edge_kernel<<<((size_t)EE * 32 + 255) / 256, 256>>>(src, dst, p_el, p_er,
                                                        p_denom, p_feat, p_agg);

    // normalize (agg /= denom) fused with BN1 column stats
    div_stats_kernel<<<1024, 128>>>(p_agg, p_denom, p_stats, p_stats + DD);
    bn_finalize_kernel<<<1, DD>>>(p_stats, p_stats + DD, bn1_gamma, bn1_beta,
                                  p_scale1, p_shift1, 1.0f / NN);

    // mid = relu(BN1(agg) @ W1 + b1)  [50000,512]
    sgemm128<true, true><<<dim3(HIDDEN / 128, (NN + 127) / 128), 256>>>(
        p_agg, W1, p_mid, NN, HIDDEN, DD, p_scale1, p_shift1, b1);

    // out_pre = mid @ W2   (b2 absorbed by BN2) -> write straight to d_out
    sgemm128<false, false><<<dim3(DD / 128, (NN + 127) / 128), 256>>>(
        p_mid, W2, out, NN, DD, HIDDEN, nullptr, nullptr, nullptr);

    // BN2 stats + in-place apply on d_out
    col_stats_kernel<<<1024, 128>>>(out, NN, p_stats + 2 * DD, p_stats + 3 * DD);
    bn_finalize_kernel<<<1, DD>>>(p_stats + 2 * DD, p_stats + 3 * DD, bn2_gamma,
                                  bn2_beta, p_scale2, p_shift2, 1.0f / NN);
    bn_apply_kernel<<<(NN * DD + 255) / 256, 256>>>(out, p_scale2, p_shift2);
}